// round 2
// baseline (speedup 1.0000x reference)
#include <cuda_runtime.h>

// LePEAttention: B=4, C=64, H=W=128, NUM_HEADS=8, hd=8, SPLIT=2
// -> H_sp=128, W_sp=2, no padding. 2048 CTAs = (batch, window, head).
// R2: 128 threads/CTA, 2 queries per thread (t and t+128). K/V smem reads are
// shared across both queries -> LDS per (q,k) pair halved (was the 91% L1 binder).

#define HW_  (128*128)
#define WW_  128
#define CC_  64
#define LOG2E 1.44269504088896340736f

__device__ __forceinline__ unsigned long long pk2(float lo, float hi) {
    unsigned long long r;
    asm("mov.b64 %0, {%1, %2};" : "=l"(r) : "f"(lo), "f"(hi));
    return r;
}
__device__ __forceinline__ void upk2(unsigned long long v, float& lo, float& hi) {
    asm("mov.b64 {%0, %1}, %2;" : "=f"(lo), "=f"(hi) : "l"(v));
}
__device__ __forceinline__ unsigned long long ffma2(unsigned long long a, unsigned long long b, unsigned long long c) {
    unsigned long long d;
    asm("fma.rn.f32x2 %0, %1, %2, %3;" : "=l"(d) : "l"(a), "l"(b), "l"(c));
    return d;
}
__device__ __forceinline__ unsigned long long fmul2(unsigned long long a, unsigned long long b) {
    unsigned long long d;
    asm("mul.rn.f32x2 %0, %1, %2;" : "=l"(d) : "l"(a), "l"(b));
    return d;
}
__device__ __forceinline__ unsigned long long fadd2(unsigned long long a, unsigned long long b) {
    unsigned long long d;
    asm("add.rn.f32x2 %0, %1, %2;" : "=l"(d) : "l"(a), "l"(b));
    return d;
}
__device__ __forceinline__ float ex2(float x) {
    float r;
    asm("ex2.approx.f32 %0, %1;" : "=f"(r) : "f"(x));
    return r;
}

__global__ void __launch_bounds__(128, 8)
lepe_kernel(const float* __restrict__ temp,
            const float* __restrict__ cw,
            const float* __restrict__ cb,
            float* __restrict__ out)
{
    const int wh  = blockIdx.x;      // 0..2047
    const int h   = wh & 7;          // head
    const int win = wh >> 3;         // 0..255
    const int b   = win >> 6;        // batch
    const int wx  = win & 63;        // window column (x in [2*wx, 2*wx+1])
    const int t   = threadIdx.x;     // 0..127; owns queries t and t+128

    // SMEM: [token][8] layout. vS has 3 guard-zero tokens each side so the
    // LePE conv taps never need a y-bounds check.
    __shared__ __align__(16) float qS[256*8];
    __shared__ __align__(16) float kS[256*8];
    __shared__ __align__(16) float vS[262*8];
    __shared__ __align__(16) float wS[9*8];
    __shared__ float bS[8];

    if (t < 24) { vS[t] = 0.f; vS[262*8 - 24 + t] = 0.f; }
    if (t < 72) wS[t] = cw[(h*8 + (t & 7))*9 + (t >> 3)];   // wS[tap][d]
    if (t < 8)  bS[t] = cb[h*8 + t];

    // Cooperative tile load: thread -> (d = t&7, y0 = t>>3 in 0..15), 8 steps.
    {
        const int d  = t & 7;
        const int y0 = t >> 3;
        const size_t cbase = (size_t)(h*8 + d) * HW_ + 2*wx;
        const float* qg = temp + (size_t)(b*3 + 0)*CC_*HW_ + cbase;
        const float* kg = temp + (size_t)(b*3 + 1)*CC_*HW_ + cbase;
        const float* vg = temp + (size_t)(b*3 + 2)*CC_*HW_ + cbase;
        #pragma unroll
        for (int i = 0; i < 8; i++) {
            int y = y0 + i*16;
            float2 q2 = *(const float2*)(qg + (size_t)y*WW_);
            float2 k2 = *(const float2*)(kg + (size_t)y*WW_);
            float2 v2 = *(const float2*)(vg + (size_t)y*WW_);
            qS[(2*y  )*8 + d] = q2.x;  qS[(2*y+1)*8 + d] = q2.y;
            kS[(2*y  )*8 + d] = k2.x;  kS[(2*y+1)*8 + d] = k2.y;
            vS[(3+2*y)*8 + d] = v2.x;  vS[(4+2*y)*8 + d] = v2.y;
        }
    }
    __syncthreads();

    // Two query rows per thread; fold scale*log2(e) into Q so softmax is a
    // bare ex2.approx per key.
    const float qscale = 0.35355339059327373f * LOG2E;  // 8^-0.5 * log2(e)
    const int tA = t, tB = t + 128;
    float4 a0 = *(const float4*)&qS[tA*8];
    float4 a1 = *(const float4*)&qS[tA*8 + 4];
    float4 b0 = *(const float4*)&qS[tB*8];
    float4 b1 = *(const float4*)&qS[tB*8 + 4];
    const unsigned long long qA01 = pk2(a0.x*qscale, a0.y*qscale);
    const unsigned long long qA23 = pk2(a0.z*qscale, a0.w*qscale);
    const unsigned long long qA45 = pk2(a1.x*qscale, a1.y*qscale);
    const unsigned long long qA67 = pk2(a1.z*qscale, a1.w*qscale);
    const unsigned long long qB01 = pk2(b0.x*qscale, b0.y*qscale);
    const unsigned long long qB23 = pk2(b0.z*qscale, b0.w*qscale);
    const unsigned long long qB45 = pk2(b1.x*qscale, b1.y*qscale);
    const unsigned long long qB67 = pk2(b1.z*qscale, b1.w*qscale);

    unsigned long long aA01 = 0ull, aA23 = 0ull, aA45 = 0ull, aA67 = 0ull;
    unsigned long long aB01 = 0ull, aB23 = 0ull, aB45 = 0ull, aB67 = 0ull;
    unsigned long long l01  = 0ull;   // packed (lA, lB)

    const ulonglong2* k128 = (const ulonglong2*)kS;
    const ulonglong2* v128 = (const ulonglong2*)(vS + 24);  // token 0 of V

    #pragma unroll 8
    for (int j = 0; j < 256; j++) {
        ulonglong2 ka = k128[j*2 + 0];   // k[j][0..3]
        ulonglong2 kb = k128[j*2 + 1];   // k[j][4..7]
        ulonglong2 va = v128[j*2 + 0];
        ulonglong2 vb = v128[j*2 + 1];

        unsigned long long dA = fmul2(qA01, ka.x);
        unsigned long long dB = fmul2(qB01, ka.x);
        dA = ffma2(qA23, ka.y, dA);
        dB = ffma2(qB23, ka.y, dB);
        dA = ffma2(qA45, kb.x, dA);
        dB = ffma2(qB45, kb.x, dB);
        dA = ffma2(qA67, kb.y, dA);
        dB = ffma2(qB67, kb.y, dB);

        float sAlo, sAhi, sBlo, sBhi;
        upk2(dA, sAlo, sAhi);
        upk2(dB, sBlo, sBhi);
        float pA = ex2(sAlo + sAhi);
        float pB = ex2(sBlo + sBhi);
        l01 = fadd2(l01, pk2(pA, pB));

        unsigned long long ppA = pk2(pA, pA);
        unsigned long long ppB = pk2(pB, pB);
        aA01 = ffma2(ppA, va.x, aA01);
        aB01 = ffma2(ppB, va.x, aB01);
        aA23 = ffma2(ppA, va.y, aA23);
        aB23 = ffma2(ppB, va.y, aB23);
        aA45 = ffma2(ppA, vb.x, aA45);
        aB45 = ffma2(ppB, vb.x, aB45);
        aA67 = ffma2(ppA, vb.y, aA67);
        aB67 = ffma2(ppB, vb.y, aB67);
    }

    float lA, lB;
    upk2(l01, lA, lB);
    const float invA = 1.0f / lA;
    const float invB = 1.0f / lB;

    // Epilogue per owned query token: softmax normalize + LePE depthwise 3x3
    // conv on the V tile in SMEM, then one float4-pair store.
    #pragma unroll
    for (int qi = 0; qi < 2; qi++) {
        const int tok = qi ? tB : tA;
        const float inv = qi ? invB : invA;
        float o[8];
        if (qi == 0) {
            upk2(aA01, o[0], o[1]); upk2(aA23, o[2], o[3]);
            upk2(aA45, o[4], o[5]); upk2(aA67, o[6], o[7]);
        } else {
            upk2(aB01, o[0], o[1]); upk2(aB23, o[2], o[3]);
            upk2(aB45, o[4], o[5]); upk2(aB67, o[6], o[7]);
        }

        const int y  = tok >> 1;
        const int xi = tok & 1;
        float r[8];
        #pragma unroll
        for (int d = 0; d < 8; d++) r[d] = bS[d];
        #pragma unroll
        for (int ky = 0; ky < 3; ky++) {
            #pragma unroll
            for (int kx = 0; kx < 3; kx++) {
                int dxi = xi + kx - 1;
                if (dxi >= 0 && dxi <= 1) {
                    int ptok = tok + (ky - 1)*2 + (kx - 1) + 3;  // padded index
                    const float4 va = *(const float4*)&vS[ptok*8];
                    const float4 vb = *(const float4*)&vS[ptok*8 + 4];
                    const float4 wa = *(const float4*)&wS[(ky*3 + kx)*8];
                    const float4 wb = *(const float4*)&wS[(ky*3 + kx)*8 + 4];
                    r[0] += va.x*wa.x;  r[1] += va.y*wa.y;
                    r[2] += va.z*wa.z;  r[3] += va.w*wa.w;
                    r[4] += vb.x*wb.x;  r[5] += vb.y*wb.y;
                    r[6] += vb.z*wb.z;  r[7] += vb.w*wb.w;
                }
            }
        }

        const size_t obase = ((size_t)b*HW_ + (size_t)y*WW_ + 2*wx + xi)*CC_ + h*8;
        float4 w0 = make_float4(o[0]*inv + r[0], o[1]*inv + r[1],
                                o[2]*inv + r[2], o[3]*inv + r[3]);
        float4 w1 = make_float4(o[4]*inv + r[4], o[5]*inv + r[5],
                                o[6]*inv + r[6], o[7]*inv + r[7]);
        *(float4*)(out + obase)     = w0;
        *(float4*)(out + obase + 4) = w1;
    }
}

extern "C" void kernel_launch(void* const* d_in, const int* in_sizes, int n_in,
                              void* d_out, int out_size)
{
    const float* temp = (const float*)d_in[0];
    const float* cw   = (const float*)d_in[1];
    const float* cb   = (const float*)d_in[2];
    float* out        = (float*)d_out;
    lepe_kernel<<<2048, 128>>>(temp, cw, cb, out);
}

// round 3
// speedup vs baseline: 1.7744x; 1.7744x over previous
#include <cuda_runtime.h>

// LePEAttention: B=4, C=64, H=W=128, NUM_HEADS=8, hd=8, SPLIT=2
// -> H_sp=128, W_sp=2, no padding. 2048 CTAs = (batch, window, head).
// R3: 128 threads/CTA, 2 queries per thread. Same as R2 but WITHOUT the
// 64-register cap (R2's __launch_bounds__(128,8) forced spills -> L1 flooded
// with LDL/STL). launch_bounds(128,4) gives a 128-reg budget; unroll 4.

#define HW_  (128*128)
#define WW_  128
#define CC_  64
#define LOG2E 1.44269504088896340736f

__device__ __forceinline__ unsigned long long pk2(float lo, float hi) {
    unsigned long long r;
    asm("mov.b64 %0, {%1, %2};" : "=l"(r) : "f"(lo), "f"(hi));
    return r;
}
__device__ __forceinline__ void upk2(unsigned long long v, float& lo, float& hi) {
    asm("mov.b64 {%0, %1}, %2;" : "=f"(lo), "=f"(hi) : "l"(v));
}
__device__ __forceinline__ unsigned long long ffma2(unsigned long long a, unsigned long long b, unsigned long long c) {
    unsigned long long d;
    asm("fma.rn.f32x2 %0, %1, %2, %3;" : "=l"(d) : "l"(a), "l"(b), "l"(c));
    return d;
}
__device__ __forceinline__ unsigned long long fmul2(unsigned long long a, unsigned long long b) {
    unsigned long long d;
    asm("mul.rn.f32x2 %0, %1, %2;" : "=l"(d) : "l"(a), "l"(b));
    return d;
}
__device__ __forceinline__ unsigned long long fadd2(unsigned long long a, unsigned long long b) {
    unsigned long long d;
    asm("add.rn.f32x2 %0, %1, %2;" : "=l"(d) : "l"(a), "l"(b));
    return d;
}
__device__ __forceinline__ float ex2(float x) {
    float r;
    asm("ex2.approx.f32 %0, %1;" : "=f"(r) : "f"(x));
    return r;
}

__global__ void __launch_bounds__(128, 4)
lepe_kernel(const float* __restrict__ temp,
            const float* __restrict__ cw,
            const float* __restrict__ cb,
            float* __restrict__ out)
{
    const int wh  = blockIdx.x;      // 0..2047
    const int h   = wh & 7;          // head
    const int win = wh >> 3;         // 0..255
    const int b   = win >> 6;        // batch
    const int wx  = win & 63;        // window column (x in [2*wx, 2*wx+1])
    const int t   = threadIdx.x;     // 0..127; owns queries t and t+128

    __shared__ __align__(16) float qS[256*8];
    __shared__ __align__(16) float kS[256*8];
    __shared__ __align__(16) float vS[262*8];   // 3 guard-zero tokens each side
    __shared__ __align__(16) float wS[9*8];
    __shared__ float bS[8];

    if (t < 24) { vS[t] = 0.f; vS[262*8 - 24 + t] = 0.f; }
    if (t < 72) wS[t] = cw[(h*8 + (t & 7))*9 + (t >> 3)];   // wS[tap][d]
    if (t < 8)  bS[t] = cb[h*8 + t];

    // Cooperative tile load: thread -> (d = t&7, y0 = t>>3 in 0..15), 8 steps.
    {
        const int d  = t & 7;
        const int y0 = t >> 3;
        const size_t cbase = (size_t)(h*8 + d) * HW_ + 2*wx;
        const float* qg = temp + (size_t)(b*3 + 0)*CC_*HW_ + cbase;
        const float* kg = temp + (size_t)(b*3 + 1)*CC_*HW_ + cbase;
        const float* vg = temp + (size_t)(b*3 + 2)*CC_*HW_ + cbase;
        #pragma unroll
        for (int i = 0; i < 8; i++) {
            int y = y0 + i*16;
            float2 q2 = *(const float2*)(qg + (size_t)y*WW_);
            float2 k2 = *(const float2*)(kg + (size_t)y*WW_);
            float2 v2 = *(const float2*)(vg + (size_t)y*WW_);
            qS[(2*y  )*8 + d] = q2.x;  qS[(2*y+1)*8 + d] = q2.y;
            kS[(2*y  )*8 + d] = k2.x;  kS[(2*y+1)*8 + d] = k2.y;
            vS[(3+2*y)*8 + d] = v2.x;  vS[(4+2*y)*8 + d] = v2.y;
        }
    }
    __syncthreads();

    // Two query rows per thread; fold scale*log2(e) into Q so softmax is a
    // bare ex2.approx per key.
    const float qscale = 0.35355339059327373f * LOG2E;  // 8^-0.5 * log2(e)
    const int tA = t, tB = t + 128;
    float4 a0 = *(const float4*)&qS[tA*8];
    float4 a1 = *(const float4*)&qS[tA*8 + 4];
    float4 b0 = *(const float4*)&qS[tB*8];
    float4 b1 = *(const float4*)&qS[tB*8 + 4];
    const unsigned long long qA01 = pk2(a0.x*qscale, a0.y*qscale);
    const unsigned long long qA23 = pk2(a0.z*qscale, a0.w*qscale);
    const unsigned long long qA45 = pk2(a1.x*qscale, a1.y*qscale);
    const unsigned long long qA67 = pk2(a1.z*qscale, a1.w*qscale);
    const unsigned long long qB01 = pk2(b0.x*qscale, b0.y*qscale);
    const unsigned long long qB23 = pk2(b0.z*qscale, b0.w*qscale);
    const unsigned long long qB45 = pk2(b1.x*qscale, b1.y*qscale);
    const unsigned long long qB67 = pk2(b1.z*qscale, b1.w*qscale);

    unsigned long long aA01 = 0ull, aA23 = 0ull, aA45 = 0ull, aA67 = 0ull;
    unsigned long long aB01 = 0ull, aB23 = 0ull, aB45 = 0ull, aB67 = 0ull;
    unsigned long long l01  = 0ull;   // packed (lA, lB)

    const ulonglong2* k128 = (const ulonglong2*)kS;
    const ulonglong2* v128 = (const ulonglong2*)(vS + 24);  // token 0 of V

    #pragma unroll 4
    for (int j = 0; j < 256; j++) {
        ulonglong2 ka = k128[j*2 + 0];   // k[j][0..3]
        ulonglong2 kb = k128[j*2 + 1];   // k[j][4..7]
        ulonglong2 va = v128[j*2 + 0];
        ulonglong2 vb = v128[j*2 + 1];

        unsigned long long dA = fmul2(qA01, ka.x);
        unsigned long long dB = fmul2(qB01, ka.x);
        dA = ffma2(qA23, ka.y, dA);
        dB = ffma2(qB23, ka.y, dB);
        dA = ffma2(qA45, kb.x, dA);
        dB = ffma2(qB45, kb.x, dB);
        dA = ffma2(qA67, kb.y, dA);
        dB = ffma2(qB67, kb.y, dB);

        float sAlo, sAhi, sBlo, sBhi;
        upk2(dA, sAlo, sAhi);
        upk2(dB, sBlo, sBhi);
        float pA = ex2(sAlo + sAhi);
        float pB = ex2(sBlo + sBhi);
        l01 = fadd2(l01, pk2(pA, pB));

        unsigned long long ppA = pk2(pA, pA);
        unsigned long long ppB = pk2(pB, pB);
        aA01 = ffma2(ppA, va.x, aA01);
        aB01 = ffma2(ppB, va.x, aB01);
        aA23 = ffma2(ppA, va.y, aA23);
        aB23 = ffma2(ppB, va.y, aB23);
        aA45 = ffma2(ppA, vb.x, aA45);
        aB45 = ffma2(ppB, vb.x, aB45);
        aA67 = ffma2(ppA, vb.y, aA67);
        aB67 = ffma2(ppB, vb.y, aB67);
    }

    float lA, lB;
    upk2(l01, lA, lB);
    const float invA = 1.0f / lA;
    const float invB = 1.0f / lB;

    // Epilogue per owned query token: softmax normalize + LePE depthwise 3x3
    // conv on the V tile in SMEM, then one float4-pair store.
    #pragma unroll
    for (int qi = 0; qi < 2; qi++) {
        const int tok = qi ? tB : tA;
        const float inv = qi ? invB : invA;
        float o[8];
        if (qi == 0) {
            upk2(aA01, o[0], o[1]); upk2(aA23, o[2], o[3]);
            upk2(aA45, o[4], o[5]); upk2(aA67, o[6], o[7]);
        } else {
            upk2(aB01, o[0], o[1]); upk2(aB23, o[2], o[3]);
            upk2(aB45, o[4], o[5]); upk2(aB67, o[6], o[7]);
        }

        const int y  = tok >> 1;
        const int xi = tok & 1;
        float r[8];
        #pragma unroll
        for (int d = 0; d < 8; d++) r[d] = bS[d];
        #pragma unroll
        for (int ky = 0; ky < 3; ky++) {
            #pragma unroll
            for (int kx = 0; kx < 3; kx++) {
                int dxi = xi + kx - 1;
                if (dxi >= 0 && dxi <= 1) {
                    int ptok = tok + (ky - 1)*2 + (kx - 1) + 3;  // padded index
                    const float4 va = *(const float4*)&vS[ptok*8];
                    const float4 vb = *(const float4*)&vS[ptok*8 + 4];
                    const float4 wa = *(const float4*)&wS[(ky*3 + kx)*8];
                    const float4 wb = *(const float4*)&wS[(ky*3 + kx)*8 + 4];
                    r[0] += va.x*wa.x;  r[1] += va.y*wa.y;
                    r[2] += va.z*wa.z;  r[3] += va.w*wa.w;
                    r[4] += vb.x*wb.x;  r[5] += vb.y*wb.y;
                    r[6] += vb.z*wb.z;  r[7] += vb.w*wb.w;
                }
            }
        }

        const size_t obase = ((size_t)b*HW_ + (size_t)y*WW_ + 2*wx + xi)*CC_ + h*8;
        float4 w0 = make_float4(o[0]*inv + r[0], o[1]*inv + r[1],
                                o[2]*inv + r[2], o[3]*inv + r[3]);
        float4 w1 = make_float4(o[4]*inv + r[4], o[5]*inv + r[5],
                                o[6]*inv + r[6], o[7]*inv + r[7]);
        *(float4*)(out + obase)     = w0;
        *(float4*)(out + obase + 4) = w1;
    }
}

extern "C" void kernel_launch(void* const* d_in, const int* in_sizes, int n_in,
                              void* d_out, int out_size)
{
    const float* temp = (const float*)d_in[0];
    const float* cw   = (const float*)d_in[1];
    const float* cb   = (const float*)d_in[2];
    float* out        = (float*)d_out;
    lepe_kernel<<<2048, 128>>>(temp, cw, cb, out);
}